// round 6
// baseline (speedup 1.0000x reference)
#include <cuda_runtime.h>
#include <cuda_fp16.h>
#include <cstdint>
#include <cstddef>

#define Bc 8
#define Sc 1024
#define Dc 1024
#define Hc 16
#define DKc 64
#define Mrows (Bc*Sc)
#define BHc (Bc*Hc)

typedef long long ll;

// ---------------- scratch ----------------
__device__ __half g_in3[(size_t)3*Mrows*3*Dc];    // z: 0=query 1=key 2=value, A-pattern [hi|hi|lo]
__device__ __half g_W3[(size_t)3*Dc*3*Dc];        // z: 0=Wq 1=Wk 2=Wv, B-pattern [hi|lo|hi]
__device__ __half g_Wps[(size_t)Dc*6*Dc];
__device__ float g_F3[(size_t)3*Mrows*Dc];        // z: 0=Qf 1=Kf 2=Vf
__device__ float g_ctxf[(size_t)Mrows*Dc];
__device__ __half g_qh[(size_t)BHc*Sc*3*DKc];     // [128][1024][192] A-pattern
__device__ __half g_kh[(size_t)BHc*Sc*3*DKc];     // B-pattern
__device__ __half g_vh[(size_t)BHc*DKc*2*Sc];     // [128][64][hi 1024 | lo 1024]
__device__ __half g_ctxs[(size_t)Mrows*3*Dc];     // ctx A-pattern
__device__ float g_part[(size_t)BHc*Sc*16];       // per-row expsum partials (16/row)

__device__ __forceinline__ uint32_t smem_u32(const void* p){
    uint32_t r;
    asm("{ .reg .u64 t; cvta.to.shared.u64 t, %1; cvt.u32.u64 %0, t; }" : "=r"(r) : "l"(p));
    return r;
}
#define SWZ(o) ((o) ^ (((o) >> 3) & 0x70))

#define LDSM4(r0,r1,r2,r3,addr) \
    asm volatile("ldmatrix.sync.aligned.m8n8.x4.shared.b16 {%0,%1,%2,%3}, [%4];" \
        : "=r"(r0), "=r"(r1), "=r"(r2), "=r"(r3) : "r"(addr))

#define MMA4(d,a,b0,b1) \
    asm volatile("mma.sync.aligned.m16n8k16.row.col.f32.f16.f16.f32 " \
        "{%0,%1,%2,%3},{%4,%5,%6,%7},{%8,%9},{%0,%1,%2,%3};" \
        : "+f"((d)[0]), "+f"((d)[1]), "+f"((d)[2]), "+f"((d)[3]) \
        : "r"((a)[0]), "r"((a)[1]), "r"((a)[2]), "r"((a)[3]), "r"(b0), "r"(b1))

#define CPA16(saddr, gptr) \
    asm volatile("cp.async.cg.shared.global [%0], [%1], 16;" :: "r"(saddr), "l"(gptr))
#define CPA_COMMIT() asm volatile("cp.async.commit_group;" ::: "memory")

__device__ __forceinline__ uint32_t pack2h(float a, float b){
    __half2 t = __floats2half2_rn(a, b);
    return *reinterpret_cast<uint32_t*>(&t);
}

// ============================================================================
// fp16 HMMA GEMM, 4-stage cp.async pipeline. CTA tile 256x128, 8 warps 64x64.
// smem: A stages [4][32KB] @0, B stages [4][16KB] @128KB (192KB total)
// rowpart != nullptr  =>  scores mode: C = exp(acc), write per-row partial sums.
// ============================================================================
__global__ __launch_bounds__(256, 1) void gemm_hmma(
    const __half* __restrict__ A0, ll ldA0, ll zA0,
    const __half* __restrict__ B0, ll ldB0, ll zB0, int nc0,
    const __half* __restrict__ A1, ll ldA1,
    const __half* __restrict__ B1, ll ldB1, int nc1,
    float* __restrict__ C, ll ldC, ll zC,
    const float* __restrict__ bias0, const float* __restrict__ bias1,
    const float* __restrict__ bias2, float* __restrict__ rowpart)
{
    extern __shared__ char sm[];
    const int tid = threadIdx.x, lane = tid & 31, wid = tid >> 5;
    const int wm = wid >> 1, wn = wid & 1;
    const int z = blockIdx.z;
    const ll bm = (ll)blockIdx.y * 256, bn = (ll)blockIdx.x * 128;
    A0 += (ll)z * zA0; B0 += (ll)z * zB0; C += (ll)z * zC;
    const uint32_t sbase = smem_u32(sm);

    float acc[4][8][4];
    #pragma unroll
    for (int i = 0; i < 4; i++)
        #pragma unroll
        for (int j = 0; j < 8; j++)
            #pragma unroll
            for (int k = 0; k < 4; k++) acc[i][j][k] = 0.f;

    const int NC = nc0 + nc1;

    auto issue = [&](int c){
        const int s = c & 3;
        const __half *Ap, *Bp; ll lda, ldb; int cc;
        if (c < nc0){ Ap = A0; lda = ldA0; Bp = B0; ldb = ldB0; cc = c; }
        else        { Ap = A1; lda = ldA1; Bp = B1; ldb = ldB1; cc = c - nc0; }
        const uint32_t as = sbase + (uint32_t)s * 32768u;
        const uint32_t bs = sbase + 131072u + (uint32_t)s * 16384u;
        #pragma unroll
        for (int j = 0; j < 8; j++){
            int v = tid + j * 256, r = v >> 3, c16 = v & 7;
            const char* g = (const char*)(Ap + (bm + r) * lda + (ll)cc * 64) + c16 * 16;
            CPA16(as + SWZ((uint32_t)r * 128u + c16 * 16u), g);
        }
        #pragma unroll
        for (int j = 0; j < 4; j++){
            int v = tid + j * 256, r = v >> 3, c16 = v & 7;
            const char* g = (const char*)(Bp + (bn + r) * ldb + (ll)cc * 64) + c16 * 16;
            CPA16(bs + SWZ((uint32_t)r * 128u + c16 * 16u), g);
        }
        CPA_COMMIT();
    };

    const int arow = wm * 64 + (lane & 7) + ((lane >> 3) & 1) * 8;
    const int acol8 = ((lane >> 4) & 1) * 8;
    const int brow = wn * 64 + (lane & 7) + ((lane >> 4) & 1) * 8;
    const int bcol8 = ((lane >> 3) & 1) * 8;

    if (0 < NC) issue(0);
    if (1 < NC) issue(1);
    if (2 < NC) issue(2);

    for (int c = 0; c < NC; c++){
        const int rem = NC - 1 - c;
        if (rem >= 2)      asm volatile("cp.async.wait_group 2;" ::: "memory");
        else if (rem == 1) asm volatile("cp.async.wait_group 1;" ::: "memory");
        else               asm volatile("cp.async.wait_group 0;" ::: "memory");
        __syncthreads();
        if (c + 3 < NC) issue(c + 3);

        const uint32_t ab = sbase + (uint32_t)(c & 3) * 32768u;
        const uint32_t bb = sbase + 131072u + (uint32_t)(c & 3) * 16384u;
        #pragma unroll
        for (int ks = 0; ks < 4; ks++){
            uint32_t a[4][4];
            #pragma unroll
            for (int mt = 0; mt < 4; mt++){
                uint32_t ad = ab + SWZ((uint32_t)(arow + mt * 16) * 128u + (ks * 16 + acol8) * 2u);
                LDSM4(a[mt][0], a[mt][1], a[mt][2], a[mt][3], ad);
            }
            #pragma unroll
            for (int np = 0; np < 4; np++){
                uint32_t b0, b1, b2, b3;
                uint32_t bd = bb + SWZ((uint32_t)(brow + np * 16) * 128u + (ks * 16 + bcol8) * 2u);
                LDSM4(b0, b1, b2, b3, bd);
                #pragma unroll
                for (int mt = 0; mt < 4; mt++){
                    MMA4(acc[mt][np * 2],     a[mt], b0, b1);
                    MMA4(acc[mt][np * 2 + 1], a[mt], b2, b3);
                }
            }
        }
        __syncthreads();
    }

    if (rowpart == nullptr){
        const float* bias = (z == 0) ? bias0 : (z == 1) ? bias1 : bias2;
        #pragma unroll
        for (int mt = 0; mt < 4; mt++){
            #pragma unroll
            for (int nt = 0; nt < 8; nt++){
                ll r0 = bm + wm * 64 + mt * 16 + (lane >> 2);
                ll col = bn + wn * 64 + nt * 8 + (lane & 3) * 2;
                float bx = 0.f, by = 0.f;
                if (bias){ bx = bias[col]; by = bias[col + 1]; }
                *(float2*)&C[r0 * ldC + col] =
                    make_float2(acc[mt][nt][0] + bx, acc[mt][nt][1] + by);
                *(float2*)&C[(r0 + 8) * ldC + col] =
                    make_float2(acc[mt][nt][2] + bx, acc[mt][nt][3] + by);
            }
        }
    } else {
        // scores mode: C = exp(acc); per-row partial sums (this CTA's 128 cols,
        // split per wn half => 16 partials per row across 8 n-blocks)
        #pragma unroll
        for (int mt = 0; mt < 4; mt++){
            float rs0 = 0.f, rs1 = 0.f;
            ll r0 = bm + wm * 64 + mt * 16 + (lane >> 2);
            #pragma unroll
            for (int nt = 0; nt < 8; nt++){
                ll col = bn + wn * 64 + nt * 8 + (lane & 3) * 2;
                float e0 = __expf(acc[mt][nt][0]), e1 = __expf(acc[mt][nt][1]);
                float e2 = __expf(acc[mt][nt][2]), e3 = __expf(acc[mt][nt][3]);
                *(float2*)&C[r0 * ldC + col] = make_float2(e0, e1);
                *(float2*)&C[(r0 + 8) * ldC + col] = make_float2(e2, e3);
                rs0 += e0 + e1; rs1 += e2 + e3;
            }
            rs0 += __shfl_xor_sync(0xffffffffu, rs0, 1);
            rs0 += __shfl_xor_sync(0xffffffffu, rs0, 2);
            rs1 += __shfl_xor_sync(0xffffffffu, rs1, 1);
            rs1 += __shfl_xor_sync(0xffffffffu, rs1, 2);
            if ((lane & 3) == 0){
                rowpart[((ll)z * Sc + r0) * 16 + blockIdx.x * 2 + wn] = rs0;
                rowpart[((ll)z * Sc + r0 + 8) * 16 + blockIdx.x * 2 + wn] = rs1;
            }
        }
    }
}

// ============================================================================
// ctx GEMM with fused softmax-normalization:
// reads exp-scores, normalizes by row sum (from partials), writes final att,
// and computes ctx = att @ V via compensated fp16 HMMA.
// ============================================================================
__global__ __launch_bounds__(256) void ctx_hmma(
    float* __restrict__ att, const __half* __restrict__ vh,
    float* __restrict__ ctxf, const float* __restrict__ part,
    const unsigned int* __restrict__ mask)
{
    extern __shared__ char sm[];
    __shared__ float s_inv[128];
    const int tid = threadIdx.x, lane = tid & 31, wid = tid >> 5;
    const int wm = wid >> 1, wn = wid & 1;
    const int z = blockIdx.z;
    const ll bm = (ll)blockIdx.y * 128;
    const uint32_t sbase = smem_u32(sm);

    // row stats: inv-sum, or -1 sentinel for masked rows
    if (tid < 128){
        int r = (int)bm + tid;
        int b = z >> 4;
        float s = 0.f;
        const float* pp = part + ((ll)z * Sc + r) * 16;
        #pragma unroll
        for (int i = 0; i < 16; i++) s += pp[i];
        s_inv[tid] = (mask[b * Sc + r] != 0u) ? -1.f : (1.0f / s);
    }

    float acc[2][4][4];
    #pragma unroll
    for (int i = 0; i < 2; i++)
        #pragma unroll
        for (int j = 0; j < 4; j++)
            #pragma unroll
            for (int k = 0; k < 4; k++) acc[i][j][k] = 0.f;

    const int row = tid >> 1, hf = tid & 1;
    float* ap = att + ((ll)z * Sc + bm + row) * Sc + hf * 32;
    const int vsel = tid >> 7, vr = (tid >> 1) & 63, vhf = tid & 1;
    const __half* vp = vh + ((ll)z * 64 + vr) * 2048 + vsel * 1024 + vhf * 32;

    const int arow = wm * 32 + (lane & 7) + ((lane >> 3) & 1) * 8;
    const int acol8 = ((lane >> 4) & 1) * 8;
    const int brow = wn * 32 + (lane & 7) + ((lane >> 4) & 1) * 8;
    const int bcol8 = ((lane >> 3) & 1) * 8;

    for (int c = 0; c < 16; c++){
        __syncthreads();
        const float inv = s_inv[row];
        #pragma unroll
        for (int j = 0; j < 4; j++){
            float4 x0 = *(const float4*)(ap + c * 64 + j * 8);
            float4 x1 = *(const float4*)(ap + c * 64 + j * 8 + 4);
            float f[8] = {x0.x, x0.y, x0.z, x0.w, x1.x, x1.y, x1.z, x1.w};
            if (inv < 0.f){
                #pragma unroll
                for (int e = 0; e < 8; e++) f[e] = 0.0009765625f;   // 1/1024
            } else {
                #pragma unroll
                for (int e = 0; e < 8; e++) f[e] *= inv;
            }
            // write final normalized att
            *(float4*)(ap + c * 64 + j * 8)     = make_float4(f[0], f[1], f[2], f[3]);
            *(float4*)(ap + c * 64 + j * 8 + 4) = make_float4(f[4], f[5], f[6], f[7]);
            float h[8], l[8];
            #pragma unroll
            for (int e = 0; e < 8; e++){
                __half hh = __float2half_rn(f[e]);
                h[e] = __half2float(hh);
                l[e] = f[e] - h[e];
            }
            uint4 Hv, Lv;
            Hv.x = pack2h(h[0], h[1]); Hv.y = pack2h(h[2], h[3]);
            Hv.z = pack2h(h[4], h[5]); Hv.w = pack2h(h[6], h[7]);
            Lv.x = pack2h(l[0], l[1]); Lv.y = pack2h(l[2], l[3]);
            Lv.z = pack2h(l[4], l[5]); Lv.w = pack2h(l[6], l[7]);
            uint32_t sw = SWZ((uint32_t)row * 128u + hf * 64u + j * 16u);
            *(uint4*)(sm + sw) = Hv;
            *(uint4*)(sm + 16384 + sw) = Lv;
        }
        {
            char* dst = sm + 32768 + vsel * 8192;
            #pragma unroll
            for (int j = 0; j < 4; j++){
                float4 v = *(const float4*)(vp + c * 64 + j * 8);
                uint32_t sw = SWZ((uint32_t)vr * 128u + vhf * 64u + j * 16u);
                *(float4*)(dst + sw) = v;
            }
        }
        __syncthreads();

        const uint32_t ah = sbase, al = sbase + 16384u;
        const uint32_t bh = sbase + 32768u, bl = sbase + 40960u;
        #pragma unroll
        for (int ks = 0; ks < 4; ks++){
            uint32_t Ah[2][4], Al[2][4];
            #pragma unroll
            for (int mt = 0; mt < 2; mt++){
                uint32_t off = SWZ((uint32_t)(arow + mt * 16) * 128u + (ks * 16 + acol8) * 2u);
                LDSM4(Ah[mt][0], Ah[mt][1], Ah[mt][2], Ah[mt][3], ah + off);
                LDSM4(Al[mt][0], Al[mt][1], Al[mt][2], Al[mt][3], al + off);
            }
            #pragma unroll
            for (int np = 0; np < 2; np++){
                uint32_t off = SWZ((uint32_t)(brow + np * 16) * 128u + (ks * 16 + bcol8) * 2u);
                uint32_t h0, h1, h2, h3, l0, l1, l2, l3;
                LDSM4(h0, h1, h2, h3, bh + off);
                LDSM4(l0, l1, l2, l3, bl + off);
                #pragma unroll
                for (int mt = 0; mt < 2; mt++){
                    MMA4(acc[mt][np * 2],     Ah[mt], h0, h1);
                    MMA4(acc[mt][np * 2 + 1], Ah[mt], h2, h3);
                    MMA4(acc[mt][np * 2],     Ah[mt], l0, l1);
                    MMA4(acc[mt][np * 2 + 1], Ah[mt], l2, l3);
                    MMA4(acc[mt][np * 2],     Al[mt], h0, h1);
                    MMA4(acc[mt][np * 2 + 1], Al[mt], h2, h3);
                }
            }
        }
    }

    const int b = z >> 4, h = z & 15;
    #pragma unroll
    for (int mt = 0; mt < 2; mt++){
        #pragma unroll
        for (int nt = 0; nt < 4; nt++){
            ll r = bm + wm * 32 + mt * 16 + (lane >> 2);
            ll col = (ll)h * 64 + wn * 32 + nt * 8 + (lane & 3) * 2;
            *(float2*)&ctxf[((ll)b * Sc + r) * Dc + col] =
                make_float2(acc[mt][nt][0], acc[mt][nt][1]);
            *(float2*)&ctxf[((ll)b * Sc + r + 8) * Dc + col] =
                make_float2(acc[mt][nt][2], acc[mt][nt][3]);
        }
    }
}

// ============================================================================
// Conversions (fp16 split) — unchanged
// ============================================================================
__global__ void splitA_dup(const float* __restrict__ X, __half* __restrict__ O, int Cdim)
{
    ll e = ((ll)blockIdx.x * blockDim.x + threadIdx.x) * 2;
    ll r = e / Cdim; int c = (int)(e % Cdim);
    float2 v = *(const float2*)(X + e);
    __half hx = __float2half_rn(v.x), hy = __float2half_rn(v.y);
    uint32_t H; { __half2 t = __halves2half2(hx, hy); H = *(uint32_t*)&t; }
    uint32_t L = pack2h(v.x - __half2float(hx), v.y - __half2float(hy));
    __half* o = O + r * (ll)(3 * Cdim) + c;
    *(uint32_t*)(o) = H; *(uint32_t*)(o + Cdim) = H; *(uint32_t*)(o + 2 * Cdim) = L;
}
__global__ void splitB(const float* __restrict__ X, ll ldin,
                       __half* __restrict__ O, ll ldout, int Cdim)
{
    ll e = ((ll)blockIdx.x * blockDim.x + threadIdx.x) * 2;
    ll r = e / Cdim; int c = (int)(e % Cdim);
    float2 v = *(const float2*)(X + r * ldin + c);
    __half hx = __float2half_rn(v.x), hy = __float2half_rn(v.y);
    uint32_t H; { __half2 t = __halves2half2(hx, hy); H = *(uint32_t*)&t; }
    uint32_t L = pack2h(v.x - __half2float(hx), v.y - __half2float(hy));
    __half* o = O + r * ldout + c;
    *(uint32_t*)(o) = H; *(uint32_t*)(o + Cdim) = L; *(uint32_t*)(o + 2 * Cdim) = H;
}
__global__ void head_split(const float* __restrict__ X, __half* __restrict__ O,
                           int offDup, int offLo, float scale)
{
    ll e = ((ll)blockIdx.x * blockDim.x + threadIdx.x) * 2;
    ll tok = e >> 10; int d = (int)(e & 1023);
    int h = d >> 6, dk = d & 63;
    ll b = tok >> 10, s = tok & 1023;
    float2 v = *(const float2*)(X + e);
    v.x *= scale; v.y *= scale;
    __half hx = __float2half_rn(v.x), hy = __float2half_rn(v.y);
    uint32_t H; { __half2 t = __halves2half2(hx, hy); H = *(uint32_t*)&t; }
    uint32_t L = pack2h(v.x - __half2float(hx), v.y - __half2float(hy));
    __half* o = O + (((ll)(b * 16 + h) * 1024 + s) * 192) + dk;
    *(uint32_t*)(o) = H; *(uint32_t*)(o + offDup) = H; *(uint32_t*)(o + offLo) = L;
}
__global__ void vT_split(const float* __restrict__ X, __half* __restrict__ O)
{
    ll e = (ll)blockIdx.x * blockDim.x + threadIdx.x;
    int kk = (int)(e & 1023); ll t = e >> 10;
    int dk = (int)(t & 63);   ll t2 = t >> 6;
    int h = (int)(t2 & 15);   int b = (int)(t2 >> 4);
    float x = X[((ll)b * 1024 + kk) * 1024 + h * 64 + dk];
    __half hx = __float2half_rn(x);
    ll o = (((ll)(b * 16 + h) * 64 + dk) * 2048) + kk;
    O[o] = hx;
    O[o + 1024] = __float2half_rn(x - __half2float(hx));
}

extern "C" void kernel_launch(void* const* d_in, const int* in_sizes, int n_in,
                              void* d_out, int out_size)
{
    (void)in_sizes; (void)n_in; (void)out_size;
    const float* key   = (const float*)d_in[0];
    const float* query = (const float*)d_in[1];
    const float* value = (const float*)d_in[2];
    const unsigned int* mask = (const unsigned int*)d_in[3];
    const float* Wk = (const float*)d_in[4];
    const float* bk = (const float*)d_in[5];
    const float* Wq = (const float*)d_in[6];
    const float* bq = (const float*)d_in[7];
    const float* Wv = (const float*)d_in[8];
    const float* bv = (const float*)d_in[9];
    const float* Wp = (const float*)d_in[10];
    const float* bp = (const float*)d_in[11];

    float* att = (float*)d_out;
    float* outp = (float*)d_out + (size_t)BHc * Sc * Sc;

    __half *in3,*W3,*wp,*qh,*kh,*vhp,*ctxs;
    float *F3,*ctxf,*part;
    cudaGetSymbolAddress((void**)&in3, g_in3);
    cudaGetSymbolAddress((void**)&W3, g_W3);
    cudaGetSymbolAddress((void**)&wp, g_Wps);
    cudaGetSymbolAddress((void**)&qh, g_qh);
    cudaGetSymbolAddress((void**)&kh, g_kh);
    cudaGetSymbolAddress((void**)&vhp, g_vh);
    cudaGetSymbolAddress((void**)&ctxs, g_ctxs);
    cudaGetSymbolAddress((void**)&F3, g_F3);
    cudaGetSymbolAddress((void**)&ctxf, g_ctxf);
    cudaGetSymbolAddress((void**)&part, g_part);

    const ll IN_Z = (ll)Mrows * 3 * Dc;
    const ll W_Z  = (ll)Dc * 3 * Dc;
    const ll F_Z  = (ll)Mrows * Dc;
    float* Qf = F3;
    float* Kf = F3 + F_Z;
    float* Vf = F3 + 2 * F_Z;

    cudaFuncSetAttribute(gemm_hmma, cudaFuncAttributeMaxDynamicSharedMemorySize, 196608);
    cudaFuncSetAttribute(ctx_hmma, cudaFuncAttributeMaxDynamicSharedMemorySize, 49152);
    const int GS = 196608, CS = 49152;

    // splits
    splitA_dup<<<(Mrows*Dc/2)/256, 256>>>(query, in3,          Dc);
    splitA_dup<<<(Mrows*Dc/2)/256, 256>>>(key,   in3 + IN_Z,   Dc);
    splitA_dup<<<(Mrows*Dc/2)/256, 256>>>(value, in3 + 2*IN_Z, Dc);
    splitB<<<(Dc*Dc/2)/256, 256>>>(Wq, Dc, W3,         3*Dc, Dc);
    splitB<<<(Dc*Dc/2)/256, 256>>>(Wk, Dc, W3 + W_Z,   3*Dc, Dc);
    splitB<<<(Dc*Dc/2)/256, 256>>>(Wv, Dc, W3 + 2*W_Z, 3*Dc, Dc);
    splitB<<<(Dc*Dc/2)/256, 256>>>(Wp,      2*Dc, wp,        6*Dc, Dc);
    splitB<<<(Dc*Dc/2)/256, 256>>>(Wp + Dc, 2*Dc, wp + 3*Dc, 6*Dc, Dc);

    // projections, batched z=3
    gemm_hmma<<<dim3(Dc/128, Mrows/256, 3), 256, GS>>>(
        in3, 3*Dc, IN_Z, W3, 3*Dc, W_Z, 48,
        in3, 3*Dc, W3, 3*Dc, 0,
        F3, Dc, F_Z, bq, bk, bv, nullptr);

    // per-head splits
    head_split<<<(Mrows*Dc/2)/256, 256>>>(Qf, qh, 64, 128, 0.125f);
    head_split<<<(Mrows*Dc/2)/256, 256>>>(Kf, kh, 128, 64, 1.0f);
    vT_split<<<(int)(((ll)BHc*DKc*Sc)/256), 256>>>(Vf, vhp);

    // scores: exp epilogue + row partials (softmax fused)
    gemm_hmma<<<dim3(Sc/128, Sc/256, BHc), 256, GS>>>(
        qh, 192, (ll)Sc*192, kh, 192, (ll)Sc*192, 3,
        qh, 192, kh, 192, 0,
        att, Sc, (ll)Sc*Sc, nullptr, nullptr, nullptr, part);

    // ctx with fused normalization + final att write
    ctx_hmma<<<dim3(1, Sc/128, BHc), 256, CS>>>(att, vhp, ctxf, part, mask);

    splitA_dup<<<(Mrows*Dc/2)/256, 256>>>(ctxf, ctxs, Dc);

    // output projection
    gemm_hmma<<<dim3(Dc/128, Mrows/256, 1), 256, GS>>>(
        in3, 3*Dc, 0, wp, 6*Dc, 0, 48,
        ctxs, 3*Dc, wp + 3*Dc, 6*Dc, 48,
        outp, Dc, 0, bp, bp, bp, nullptr);
}